// round 2
// baseline (speedup 1.0000x reference)
#include <cuda_runtime.h>

#define Bb 4
#define Tt 512
#define Cc 128
#define NEG_INF (-1e22f)
#define TI 16
#define JT 64

// scratch for Q = x@WQ, K = x@WK  (device globals: no dynamic allocation)
__device__ float g_q[Bb * Tt * Cc];
__device__ float g_k[Bb * Tt * Cc];

// ---------------------------------------------------------------------------
// Kernel 1: Q,K projection. Block = 32 rows of x; 256 threads:
// threads 0..127 compute Q columns, 128..255 compute K columns.
// ---------------------------------------------------------------------------
__global__ void __launch_bounds__(256) qk_kernel(const float* __restrict__ x,
                                                 const float* __restrict__ WQ,
                                                 const float* __restrict__ WK) {
    __shared__ float4 xs[32 * 32];  // 32 rows x 128 floats (as float4)
    const int tid  = threadIdx.x;
    const int row0 = blockIdx.x * 32;

    // cooperative coalesced load of the 32-row x tile
#pragma unroll
    for (int t = 0; t < 4; t++) {
        int f4 = tid + 256 * t;          // 0..1023
        int r  = f4 >> 5, c = f4 & 31;
        xs[f4] = ((const float4*)(x + (size_t)(row0 + r) * Cc))[c];
    }
    __syncthreads();

    const int    col = tid & 127;
    const float* W   = (tid < 128) ? WQ : WK;
    float*       OUT = (tid < 128) ? g_q : g_k;

    float acc[32];
#pragma unroll
    for (int r = 0; r < 32; r++) acc[r] = 0.f;

    for (int d4 = 0; d4 < 32; d4++) {
        float w0 = W[(4 * d4 + 0) * Cc + col];
        float w1 = W[(4 * d4 + 1) * Cc + col];
        float w2 = W[(4 * d4 + 2) * Cc + col];
        float w3 = W[(4 * d4 + 3) * Cc + col];
#pragma unroll
        for (int r = 0; r < 32; r++) {
            float4 xv = xs[r * 32 + d4];  // broadcast across warp
            acc[r] += xv.x * w0;
            acc[r] += xv.y * w1;
            acc[r] += xv.z * w2;
            acc[r] += xv.w * w3;
        }
    }
#pragma unroll
    for (int r = 0; r < 32; r++)
        OUT[(size_t)(row0 + r) * Cc + col] = acc[r];
}

// ---------------------------------------------------------------------------
// Kernel 2: fused score + masked softmax + AV.
// Grid: (T/TI, B). Block: 256 threads, one 16-row i-tile.
// Dynamic smem layout (floats):
//   ks  [0      .. 2112)   16 x 132 (padded)
//   ps  [2112   .. 2240)   128
//   qs  [2240   .. 10688)  64 x 132 (padded)  — reused as xs in AV phase
//   sc  [10688  .. 18880)  16 x 512 scores
// ---------------------------------------------------------------------------
#define SMEM_FLOATS 18880
#define SMEM_BYTES  (SMEM_FLOATS * 4)

__global__ void __launch_bounds__(256) attn_kernel(const float* __restrict__ x,
                                                   const float* __restrict__ adj,
                                                   const float* __restrict__ p,
                                                   float* __restrict__ out) {
    extern __shared__ float smem[];
    float* ks = smem;           // 16 x 132
    float* ps = smem + 2112;    // 128
    float* qs = smem + 2240;    // 64 x 132
    float* sc = smem + 10688;   // 16 x 512

    const int tid = threadIdx.x;
    const int b   = blockIdx.y;
    const int i0  = blockIdx.x * TI;

    // --- stage k tile (16x128) and p ---
#pragma unroll
    for (int t = 0; t < 2; t++) {
        int f4 = tid + 256 * t;  // 0..511
        int r  = f4 >> 5, c = f4 & 31;
        float4 v = ((const float4*)(g_k + (size_t)(b * Tt + i0 + r) * Cc))[c];
        ((float4*)(ks + r * 132))[c] = v;
    }
    if (tid < 32) ((float4*)ps)[tid] = ((const float4*)p)[tid];

    const int il2 = tid >> 5;  // 0..7 -> rows 2*il2, 2*il2+1
    const int jl  = tid & 31;  // 0..31 -> j = jl, jl+32 within chunk

    // ================= score phase =================
    for (int jc = 0; jc < Tt; jc += JT) {
        __syncthreads();
        // stage 64-row q chunk
#pragma unroll
        for (int t = 0; t < 8; t++) {
            int f4 = tid + 256 * t;  // 0..2047
            int r  = f4 >> 5, c = f4 & 31;
            float4 v = ((const float4*)(g_q + (size_t)(b * Tt + jc + r) * Cc))[c];
            ((float4*)(qs + r * 132))[c] = v;
        }
        __syncthreads();

        float a00 = 0.f, a01 = 0.f, a10 = 0.f, a11 = 0.f;
        const float4* k0p = (const float4*)(ks + (2 * il2) * 132);
        const float4* k1p = (const float4*)(ks + (2 * il2 + 1) * 132);
        const float4* q0p = (const float4*)(qs + jl * 132);
        const float4* q1p = (const float4*)(qs + (jl + 32) * 132);
        const float4* pp  = (const float4*)ps;

#pragma unroll 8
        for (int d4 = 0; d4 < 32; d4++) {
            float4 pv = pp[d4];
            float4 k0 = k0p[d4];
            float4 k1 = k1p[d4];
            float4 q0 = q0p[d4];
            float4 q1 = q1p[d4];

            a00 += pv.x * fmaxf(q0.x + k0.x, 0.f) + pv.y * fmaxf(q0.y + k0.y, 0.f)
                 + pv.z * fmaxf(q0.z + k0.z, 0.f) + pv.w * fmaxf(q0.w + k0.w, 0.f);
            a01 += pv.x * fmaxf(q1.x + k0.x, 0.f) + pv.y * fmaxf(q1.y + k0.y, 0.f)
                 + pv.z * fmaxf(q1.z + k0.z, 0.f) + pv.w * fmaxf(q1.w + k0.w, 0.f);
            a10 += pv.x * fmaxf(q0.x + k1.x, 0.f) + pv.y * fmaxf(q0.y + k1.y, 0.f)
                 + pv.z * fmaxf(q0.z + k1.z, 0.f) + pv.w * fmaxf(q0.w + k1.w, 0.f);
            a11 += pv.x * fmaxf(q1.x + k1.x, 0.f) + pv.y * fmaxf(q1.y + k1.y, 0.f)
                 + pv.z * fmaxf(q1.z + k1.z, 0.f) + pv.w * fmaxf(q1.w + k1.w, 0.f);
        }
        sc[(2 * il2) * Tt + jc + jl]          = a00;
        sc[(2 * il2) * Tt + jc + jl + 32]     = a01;
        sc[(2 * il2 + 1) * Tt + jc + jl]      = a10;
        sc[(2 * il2 + 1) * Tt + jc + jl + 32] = a11;
    }
    __syncthreads();

    // ================= masked softmax (per warp: 2 rows) =================
    const int warp = tid >> 5, lane = tid & 31;
#pragma unroll
    for (int rr = 0; rr < 2; rr++) {
        int r = 2 * warp + rr;
        const float* arow = adj + ((size_t)(b * Tt) + i0 + r) * Tt;
        float v[16];
        float m = -3.4e38f;
#pragma unroll
        for (int t = 0; t < 16; t++) {
            int   j = lane + 32 * t;
            float s = sc[r * Tt + j];
            s = (arow[j] > 0.f) ? s : NEG_INF;  // fp32 absorbs s into -1e22, same as ref
            v[t] = s;
            m = fmaxf(m, s);
        }
#pragma unroll
        for (int o = 16; o; o >>= 1) m = fmaxf(m, __shfl_xor_sync(0xffffffff, m, o));
        float sum = 0.f;
#pragma unroll
        for (int t = 0; t < 16; t++) {
            v[t] = __expf(v[t] - m);
            sum += v[t];
        }
#pragma unroll
        for (int o = 16; o; o >>= 1) sum += __shfl_xor_sync(0xffffffff, sum, o);
        float inv = 1.f / sum;
#pragma unroll
        for (int t = 0; t < 16; t++) sc[r * Tt + lane + 32 * t] = v[t] * inv;
    }
    __syncthreads();

    // ================= AV phase: out[i,:] = sum_j w[i][j] * x[j,:] =========
    const int dg = tid & 31;  // float4 column
    float4 acc0 = make_float4(0.f, 0.f, 0.f, 0.f);
    float4 acc1 = make_float4(0.f, 0.f, 0.f, 0.f);
    float* xs = qs;  // reuse q staging buffer

    for (int jc = 0; jc < Tt; jc += JT) {
        // stage 64-row x chunk
#pragma unroll
        for (int t = 0; t < 8; t++) {
            int f4 = tid + 256 * t;
            int r  = f4 >> 5, c = f4 & 31;
            ((float4*)(xs + r * 132))[c] =
                ((const float4*)(x + (size_t)(b * Tt + jc + r) * Cc))[c];
        }
        __syncthreads();

        const float* w0row = sc + (2 * il2) * Tt + jc;
        const float* w1row = w0row + Tt;
#pragma unroll 4
        for (int j = 0; j < JT; j++) {
            float  w0 = w0row[j];
            float  w1 = w1row[j];
            float4 xv = ((const float4*)(xs + j * 132))[dg];
            acc0.x += w0 * xv.x; acc0.y += w0 * xv.y;
            acc0.z += w0 * xv.z; acc0.w += w0 * xv.w;
            acc1.x += w1 * xv.x; acc1.y += w1 * xv.y;
            acc1.z += w1 * xv.z; acc1.w += w1 * xv.w;
        }
        __syncthreads();
    }
    ((float4*)(out + (size_t)(b * Tt + i0 + 2 * il2) * Cc))[dg]     = acc0;
    ((float4*)(out + (size_t)(b * Tt + i0 + 2 * il2 + 1) * Cc))[dg] = acc1;
}

// ---------------------------------------------------------------------------
extern "C" void kernel_launch(void* const* d_in, const int* in_sizes, int n_in,
                              void* d_out, int out_size) {
    const float* x   = (const float*)d_in[0];
    const float* adj = (const float*)d_in[1];
    const float* WQ  = (const float*)d_in[2];
    const float* WK  = (const float*)d_in[3];
    const float* p   = (const float*)d_in[4];
    float*       out = (float*)d_out;

    qk_kernel<<<(Bb * Tt) / 32, 256>>>(x, WQ, WK);

    cudaFuncSetAttribute(attn_kernel, cudaFuncAttributeMaxDynamicSharedMemorySize,
                         SMEM_BYTES);
    attn_kernel<<<dim3(Tt / TI, Bb), 256, SMEM_BYTES>>>(x, adj, p, out);
}

// round 3
// speedup vs baseline: 1.2895x; 1.2895x over previous
#include <cuda_runtime.h>

#define Bb 4
#define Tt 512
#define Cc 128
#define NEG_INF (-1e22f)
#define TI 16
#define JT 256

// scratch for Q = x@WQ, K = x@WK
__device__ float g_q[Bb * Tt * Cc];
__device__ float g_k[Bb * Tt * Cc];

// ---- packed f32x2 helpers -------------------------------------------------
__device__ __forceinline__ unsigned long long addrelu2(unsigned long long a,
                                                       unsigned long long b) {
    unsigned long long s;
    asm("add.rn.f32x2 %0, %1, %2;" : "=l"(s) : "l"(a), "l"(b));
    asm("{\n\t"
        ".reg .f32 lo, hi;\n\t"
        "mov.b64 {lo, hi}, %0;\n\t"
        "max.f32 lo, lo, 0f00000000;\n\t"
        "max.f32 hi, hi, 0f00000000;\n\t"
        "mov.b64 %0, {lo, hi};\n\t"
        "}"
        : "+l"(s));
    return s;
}
__device__ __forceinline__ void fma2(unsigned long long& acc, unsigned long long a,
                                     unsigned long long b) {
    asm("fma.rn.f32x2 %0, %1, %2, %0;" : "+l"(acc) : "l"(a), "l"(b));
}
__device__ __forceinline__ float hsum2(unsigned long long a) {
    float lo = __uint_as_float((unsigned)(a & 0xffffffffull));
    float hi = __uint_as_float((unsigned)(a >> 32));
    return lo + hi;
}

// ---------------------------------------------------------------------------
// Kernel 1: Q or K projection. Grid (128, 2): y=0 -> Q, y=1 -> K.
// Block: 256 threads, 16 rows x 128 cols. Thread: 8 rows, 1 col.
// ---------------------------------------------------------------------------
__global__ void __launch_bounds__(256) qk_kernel(const float* __restrict__ x,
                                                 const float* __restrict__ WQ,
                                                 const float* __restrict__ WK) {
    __shared__ float4 xs[16 * 32];  // 16 rows x 128 floats
    const int tid  = threadIdx.x;
    const int row0 = blockIdx.x * 16;
    const float* W   = blockIdx.y ? WK : WQ;
    float*       OUT = blockIdx.y ? g_k : g_q;

#pragma unroll
    for (int t = 0; t < 2; t++) {
        int f4 = tid + 256 * t;  // 0..511
        int r = f4 >> 5, c = f4 & 31;
        xs[f4] = ((const float4*)(x + (size_t)(row0 + r) * Cc))[c];
    }
    __syncthreads();

    const int col = tid & 127;
    const int rh  = tid >> 7;  // 0/1 -> rows rh*8 .. rh*8+7

    float acc[8];
#pragma unroll
    for (int r = 0; r < 8; r++) acc[r] = 0.f;

#pragma unroll 4
    for (int d4 = 0; d4 < 32; d4++) {
        float w0 = W[(4 * d4 + 0) * Cc + col];
        float w1 = W[(4 * d4 + 1) * Cc + col];
        float w2 = W[(4 * d4 + 2) * Cc + col];
        float w3 = W[(4 * d4 + 3) * Cc + col];
#pragma unroll
        for (int r = 0; r < 8; r++) {
            float4 xv = xs[(rh * 8 + r) * 32 + d4];
            acc[r] += xv.x * w0;
            acc[r] += xv.y * w1;
            acc[r] += xv.z * w2;
            acc[r] += xv.w * w3;
        }
    }
#pragma unroll
    for (int r = 0; r < 8; r++)
        OUT[(size_t)(row0 + rh * 8 + r) * Cc + col] = acc[r];
}

// ---------------------------------------------------------------------------
// Kernel 2: fused score + masked softmax + AV.
// Grid (32, 4). Block: 256 threads, one 16-row i-tile.
// smem (floats): ks 16x132 [0,2112) | ps 128 [2112,2240)
//                qs 256x132 [2240,36032) | sc 16x512 [36032,44224)
// ---------------------------------------------------------------------------
#define SMEM_FLOATS 44224
#define SMEM_BYTES  (SMEM_FLOATS * 4)

__global__ void __launch_bounds__(256) attn_kernel(const float* __restrict__ x,
                                                   const float* __restrict__ adj,
                                                   const float* __restrict__ p,
                                                   float* __restrict__ out) {
    extern __shared__ float smem[];
    float* ks = smem;          // 16 x 132
    float* ps = smem + 2112;   // 128
    float* qs = smem + 2240;   // 256 x 132 (reused as xs)
    float* sc = smem + 36032;  // 16 x 512

    const int tid = threadIdx.x;
    const int b   = blockIdx.y;
    const int i0  = blockIdx.x * TI;

    // stage k tile (16x128) + p
#pragma unroll
    for (int t = 0; t < 2; t++) {
        int f4 = tid + 256 * t;  // 0..511
        int r = f4 >> 5, c = f4 & 31;
        float4 v = ((const float4*)(g_k + (size_t)(b * Tt + i0 + r) * Cc))[c];
        ((float4*)(ks + r * 132))[c] = v;
    }
    if (tid < 32) ((float4*)ps)[tid] = ((const float4*)p)[tid];

    const int ig = tid >> 6;  // 0..3 -> rows 4ig..4ig+3 (warp-uniform)
    const int jl = tid & 63;  // j = jc + jl + 64*jt

    // ======================= score phase (4i x 4j, f32x2) ==================
    for (int jc = 0; jc < Tt; jc += JT) {
        __syncthreads();
        // stage 256-row q chunk
#pragma unroll 4
        for (int t = 0; t < 32; t++) {
            int f4 = tid + 256 * t;  // 0..8191
            int r = f4 >> 5, c = f4 & 31;
            float4 v = ((const float4*)(g_q + (size_t)(b * Tt + jc + r) * Cc))[c];
            ((float4*)(qs + r * 132))[c] = v;
        }
        __syncthreads();

        unsigned long long acc[4][4];
#pragma unroll
        for (int r = 0; r < 4; r++)
#pragma unroll
            for (int j = 0; j < 4; j++) acc[r][j] = 0ull;

        const ulonglong2* pp  = (const ulonglong2*)ps;
        const ulonglong2* k0p = (const ulonglong2*)(ks + (4 * ig + 0) * 132);
        const ulonglong2* k1p = (const ulonglong2*)(ks + (4 * ig + 1) * 132);
        const ulonglong2* k2p = (const ulonglong2*)(ks + (4 * ig + 2) * 132);
        const ulonglong2* k3p = (const ulonglong2*)(ks + (4 * ig + 3) * 132);
        const ulonglong2* q0p = (const ulonglong2*)(qs + (jl + 0) * 132);
        const ulonglong2* q1p = (const ulonglong2*)(qs + (jl + 64) * 132);
        const ulonglong2* q2p = (const ulonglong2*)(qs + (jl + 128) * 132);
        const ulonglong2* q3p = (const ulonglong2*)(qs + (jl + 192) * 132);

#pragma unroll 4
        for (int d4 = 0; d4 < 32; d4++) {
            ulonglong2 pv = pp[d4];
            ulonglong2 k0 = k0p[d4], k1 = k1p[d4], k2 = k2p[d4], k3 = k3p[d4];
            ulonglong2 q0 = q0p[d4], q1 = q1p[d4], q2 = q2p[d4], q3 = q3p[d4];

#define SCORE_RJ(r, kk, j, qq)                       \
    fma2(acc[r][j], pv.x, addrelu2(qq.x, kk.x));     \
    fma2(acc[r][j], pv.y, addrelu2(qq.y, kk.y));

            SCORE_RJ(0, k0, 0, q0) SCORE_RJ(0, k0, 1, q1)
            SCORE_RJ(0, k0, 2, q2) SCORE_RJ(0, k0, 3, q3)
            SCORE_RJ(1, k1, 0, q0) SCORE_RJ(1, k1, 1, q1)
            SCORE_RJ(1, k1, 2, q2) SCORE_RJ(1, k1, 3, q3)
            SCORE_RJ(2, k2, 0, q0) SCORE_RJ(2, k2, 1, q1)
            SCORE_RJ(2, k2, 2, q2) SCORE_RJ(2, k2, 3, q3)
            SCORE_RJ(3, k3, 0, q0) SCORE_RJ(3, k3, 1, q1)
            SCORE_RJ(3, k3, 2, q2) SCORE_RJ(3, k3, 3, q3)
#undef SCORE_RJ
        }

#pragma unroll
        for (int r = 0; r < 4; r++)
#pragma unroll
            for (int j = 0; j < 4; j++)
                sc[(4 * ig + r) * Tt + jc + jl + 64 * j] = hsum2(acc[r][j]);
    }
    __syncthreads();

    // ======================= masked softmax (8 warps x 2 rows) =============
    const int warp = tid >> 5, lane = tid & 31;
#pragma unroll
    for (int rr = 0; rr < 2; rr++) {
        int r = 2 * warp + rr;
        const float* arow = adj + ((size_t)(b * Tt) + i0 + r) * Tt;
        float v[16];
        float m = -3.4e38f;
#pragma unroll
        for (int t = 0; t < 16; t++) {
            int   j = lane + 32 * t;
            float s = sc[r * Tt + j];
            s    = (arow[j] > 0.f) ? s : NEG_INF;
            v[t] = s;
            m    = fmaxf(m, s);
        }
#pragma unroll
        for (int o = 16; o; o >>= 1) m = fmaxf(m, __shfl_xor_sync(0xffffffff, m, o));
        float sum = 0.f;
#pragma unroll
        for (int t = 0; t < 16; t++) {
            v[t] = __expf(v[t] - m);
            sum += v[t];
        }
#pragma unroll
        for (int o = 16; o; o >>= 1) sum += __shfl_xor_sync(0xffffffff, sum, o);
        float inv = 1.f / sum;
#pragma unroll
        for (int t = 0; t < 16; t++) sc[r * Tt + lane + 32 * t] = v[t] * inv;
    }

    // ======================= AV phase =======================================
    // 8 warps: warps 0-3 rows {4w..4w+3} on j-half 0, warps 4-7 same rows on
    // j-half 1; partial sums reduced through smem at the end.
    const int rg    = warp & 3;   // row group: rows 4rg..4rg+3
    const int jhalf = warp >> 2;  // 0/1

    float4 acc0 = make_float4(0, 0, 0, 0), acc1 = make_float4(0, 0, 0, 0);
    float4 acc2 = make_float4(0, 0, 0, 0), acc3 = make_float4(0, 0, 0, 0);

    for (int jc = 0; jc < Tt; jc += JT) {
        __syncthreads();
        // stage 256-row x chunk into qs
#pragma unroll 4
        for (int t = 0; t < 32; t++) {
            int f4 = tid + 256 * t;
            int r = f4 >> 5, c = f4 & 31;
            ((float4*)(qs + r * 132))[c] =
                ((const float4*)(x + (size_t)(b * Tt + jc + r) * Cc))[c];
        }
        __syncthreads();

        const float* w0row = sc + (4 * rg + 0) * Tt + jc;
        const float* w1row = sc + (4 * rg + 1) * Tt + jc;
        const float* w2row = sc + (4 * rg + 2) * Tt + jc;
        const float* w3row = sc + (4 * rg + 3) * Tt + jc;
        const int jbase = jhalf * 128;
#pragma unroll 4
        for (int jj = jbase; jj < jbase + 128; jj++) {
            float  w0 = w0row[jj], w1 = w1row[jj], w2 = w2row[jj], w3 = w3row[jj];
            float4 xv = ((const float4*)(qs + jj * 132))[lane];
            acc0.x += w0 * xv.x; acc0.y += w0 * xv.y; acc0.z += w0 * xv.z; acc0.w += w0 * xv.w;
            acc1.x += w1 * xv.x; acc1.y += w1 * xv.y; acc1.z += w1 * xv.z; acc1.w += w1 * xv.w;
            acc2.x += w2 * xv.x; acc2.y += w2 * xv.y; acc2.z += w2 * xv.z; acc2.w += w2 * xv.w;
            acc3.x += w3 * xv.x; acc3.y += w3 * xv.y; acc3.z += w3 * xv.z; acc3.w += w3 * xv.w;
        }
    }
    __syncthreads();

    // reduce j-halves through smem (reuse qs)
    float4* buf = (float4*)qs;
    if (jhalf == 1) {
        buf[(4 * rg + 0) * 32 + lane] = acc0;
        buf[(4 * rg + 1) * 32 + lane] = acc1;
        buf[(4 * rg + 2) * 32 + lane] = acc2;
        buf[(4 * rg + 3) * 32 + lane] = acc3;
    }
    __syncthreads();
    if (jhalf == 0) {
        float4 b0 = buf[(4 * rg + 0) * 32 + lane];
        float4 b1 = buf[(4 * rg + 1) * 32 + lane];
        float4 b2 = buf[(4 * rg + 2) * 32 + lane];
        float4 b3 = buf[(4 * rg + 3) * 32 + lane];
        acc0.x += b0.x; acc0.y += b0.y; acc0.z += b0.z; acc0.w += b0.w;
        acc1.x += b1.x; acc1.y += b1.y; acc1.z += b1.z; acc1.w += b1.w;
        acc2.x += b2.x; acc2.y += b2.y; acc2.z += b2.z; acc2.w += b2.w;
        acc3.x += b3.x; acc3.y += b3.y; acc3.z += b3.z; acc3.w += b3.w;
        ((float4*)(out + (size_t)(b * Tt + i0 + 4 * rg + 0) * Cc))[lane] = acc0;
        ((float4*)(out + (size_t)(b * Tt + i0 + 4 * rg + 1) * Cc))[lane] = acc1;
        ((float4*)(out + (size_t)(b * Tt + i0 + 4 * rg + 2) * Cc))[lane] = acc2;
        ((float4*)(out + (size_t)(b * Tt + i0 + 4 * rg + 3) * Cc))[lane] = acc3;
    }
}

// ---------------------------------------------------------------------------
extern "C" void kernel_launch(void* const* d_in, const int* in_sizes, int n_in,
                              void* d_out, int out_size) {
    const float* x   = (const float*)d_in[0];
    const float* adj = (const float*)d_in[1];
    const float* WQ  = (const float*)d_in[2];
    const float* WK  = (const float*)d_in[3];
    const float* p   = (const float*)d_in[4];
    float*       out = (float*)d_out;

    qk_kernel<<<dim3((Bb * Tt) / 16, 2), 256>>>(x, WQ, WK);

    cudaFuncSetAttribute(attn_kernel, cudaFuncAttributeMaxDynamicSharedMemorySize,
                         SMEM_BYTES);
    attn_kernel<<<dim3(Tt / TI, Bb), 256, SMEM_BYTES>>>(x, adj, p, out);
}

// round 4
// speedup vs baseline: 1.5444x; 1.1977x over previous
#include <cuda_runtime.h>

#define Bb 4
#define Tt 512
#define Cc 128
#define NEG_INF (-1e22f)
#define TI 16
#define JT 256

__device__ float g_q[Bb * Tt * Cc];
__device__ float g_k[Bb * Tt * Cc];

// ---- packed f32x2 helpers -------------------------------------------------
typedef unsigned long long u64;

__device__ __forceinline__ u64 addrelu2(u64 a, u64 b) {
    u64 s;
    asm("add.rn.f32x2 %0, %1, %2;" : "=l"(s) : "l"(a), "l"(b));
    asm("{\n\t"
        ".reg .f32 lo, hi;\n\t"
        "mov.b64 {lo, hi}, %0;\n\t"
        "max.f32 lo, lo, 0f00000000;\n\t"
        "max.f32 hi, hi, 0f00000000;\n\t"
        "mov.b64 %0, {lo, hi};\n\t"
        "}"
        : "+l"(s));
    return s;
}
__device__ __forceinline__ void fma2(u64& acc, u64 a, u64 b) {
    asm("fma.rn.f32x2 %0, %1, %2, %0;" : "+l"(acc) : "l"(a), "l"(b));
}
__device__ __forceinline__ u64 add2(u64 a, u64 b) {
    u64 s;
    asm("add.rn.f32x2 %0, %1, %2;" : "=l"(s) : "l"(a), "l"(b));
    return s;
}
__device__ __forceinline__ u64 dup2(float w) {
    u64 r;
    asm("mov.b64 %0, {%1, %1};" : "=l"(r) : "f"(w));
    return r;
}
__device__ __forceinline__ float lo2(u64 a) { return __uint_as_float((unsigned)a); }
__device__ __forceinline__ float hi2(u64 a) { return __uint_as_float((unsigned)(a >> 32)); }
__device__ __forceinline__ float hsum2(u64 a) { return lo2(a) + hi2(a); }

// ---------------------------------------------------------------------------
// Kernel 1: Q/K projection. Grid (128, 2): y=0 -> Q, y=1 -> K.
// ---------------------------------------------------------------------------
__global__ void __launch_bounds__(256) qk_kernel(const float* __restrict__ x,
                                                 const float* __restrict__ WQ,
                                                 const float* __restrict__ WK) {
    __shared__ float4 xs[16 * 32];
    const int tid  = threadIdx.x;
    const int row0 = blockIdx.x * 16;
    const float* W   = blockIdx.y ? WK : WQ;
    float*       OUT = blockIdx.y ? g_k : g_q;

#pragma unroll
    for (int t = 0; t < 2; t++) {
        int f4 = tid + 256 * t;
        int r = f4 >> 5, c = f4 & 31;
        xs[f4] = ((const float4*)(x + (size_t)(row0 + r) * Cc))[c];
    }
    __syncthreads();

    const int col = tid & 127;
    const int rh  = tid >> 7;

    float acc[8];
#pragma unroll
    for (int r = 0; r < 8; r++) acc[r] = 0.f;

#pragma unroll 4
    for (int d4 = 0; d4 < 32; d4++) {
        float w0 = W[(4 * d4 + 0) * Cc + col];
        float w1 = W[(4 * d4 + 1) * Cc + col];
        float w2 = W[(4 * d4 + 2) * Cc + col];
        float w3 = W[(4 * d4 + 3) * Cc + col];
#pragma unroll
        for (int r = 0; r < 8; r++) {
            float4 xv = xs[(rh * 8 + r) * 32 + d4];
            acc[r] += xv.x * w0;
            acc[r] += xv.y * w1;
            acc[r] += xv.z * w2;
            acc[r] += xv.w * w3;
        }
    }
#pragma unroll
    for (int r = 0; r < 8; r++)
        OUT[(size_t)(row0 + rh * 8 + r) * Cc + col] = acc[r];
}

// ---------------------------------------------------------------------------
// Kernel 2: fused score + masked softmax + AV. 512 threads/block.
// Grid (32, 4). smem (floats): ks 16x132 | ps 128 | qs 256x132 | sc 16x512
// ---------------------------------------------------------------------------
#define SMEM_FLOATS 44224
#define SMEM_BYTES  (SMEM_FLOATS * 4)

__global__ void __launch_bounds__(512) attn_kernel(const float* __restrict__ x,
                                                   const float* __restrict__ adj,
                                                   const float* __restrict__ p,
                                                   float* __restrict__ out) {
    extern __shared__ float smem[];
    float* ks = smem;          // 16 x 132
    float* ps = smem + 2112;   // 128
    float* qs = smem + 2240;   // 256 x 132 (reused as xs, then as reduce buf)
    float* sc = smem + 36032;  // 16 x 512

    const int tid = threadIdx.x;
    const int b   = blockIdx.y;
    const int i0  = blockIdx.x * TI;

    // stage k tile (16x128) + p
    {
        int r = tid >> 5, c = tid & 31;  // tid 0..511 covers all 512 float4
        float4 v = ((const float4*)(g_k + (size_t)(b * Tt + i0 + r) * Cc))[c];
        ((float4*)(ks + r * 132))[c] = v;
    }
    if (tid < 32) ((float4*)ps)[tid] = ((const float4*)p)[tid];

    const int ig = tid >> 6;  // 0..7 -> rows 2ig, 2ig+1
    const int jl = tid & 63;

    // ================= score phase (2i x 4j per thread, f32x2) =============
    for (int jc = 0; jc < Tt; jc += JT) {
        __syncthreads();
#pragma unroll 4
        for (int t = 0; t < 16; t++) {
            int f4 = tid + 512 * t;  // 0..8191
            int r = f4 >> 5, c = f4 & 31;
            float4 v = ((const float4*)(g_q + (size_t)(b * Tt + jc + r) * Cc))[c];
            ((float4*)(qs + r * 132))[c] = v;
        }
        __syncthreads();

        u64 acc[2][4];
#pragma unroll
        for (int r = 0; r < 2; r++)
#pragma unroll
            for (int j = 0; j < 4; j++) acc[r][j] = 0ull;

        const ulonglong2* pp  = (const ulonglong2*)ps;
        const ulonglong2* k0p = (const ulonglong2*)(ks + (2 * ig + 0) * 132);
        const ulonglong2* k1p = (const ulonglong2*)(ks + (2 * ig + 1) * 132);
        const ulonglong2* q0p = (const ulonglong2*)(qs + (jl + 0) * 132);
        const ulonglong2* q1p = (const ulonglong2*)(qs + (jl + 64) * 132);
        const ulonglong2* q2p = (const ulonglong2*)(qs + (jl + 128) * 132);
        const ulonglong2* q3p = (const ulonglong2*)(qs + (jl + 192) * 132);

#pragma unroll 4
        for (int d4 = 0; d4 < 32; d4++) {
            ulonglong2 pv = pp[d4];
            ulonglong2 k0 = k0p[d4], k1 = k1p[d4];
            ulonglong2 q0 = q0p[d4], q1 = q1p[d4], q2 = q2p[d4], q3 = q3p[d4];

#define SCORE_RJ(r, kk, j, qq)                   \
    fma2(acc[r][j], pv.x, addrelu2(qq.x, kk.x)); \
    fma2(acc[r][j], pv.y, addrelu2(qq.y, kk.y));

            SCORE_RJ(0, k0, 0, q0) SCORE_RJ(0, k0, 1, q1)
            SCORE_RJ(0, k0, 2, q2) SCORE_RJ(0, k0, 3, q3)
            SCORE_RJ(1, k1, 0, q0) SCORE_RJ(1, k1, 1, q1)
            SCORE_RJ(1, k1, 2, q2) SCORE_RJ(1, k1, 3, q3)
#undef SCORE_RJ
        }

#pragma unroll
        for (int r = 0; r < 2; r++)
#pragma unroll
            for (int j = 0; j < 4; j++)
                sc[(2 * ig + r) * Tt + jc + jl + 64 * j] = hsum2(acc[r][j]);
    }
    __syncthreads();

    // ================= masked softmax (16 warps x 1 row) ====================
    const int warp = tid >> 5, lane = tid & 31;
    {
        int r = warp;  // 0..15
        const float* arow = adj + ((size_t)(b * Tt) + i0 + r) * Tt;
        float v[16];
        float m = -3.4e38f;
#pragma unroll
        for (int t = 0; t < 16; t++) {
            int   j = lane + 32 * t;
            float s = sc[r * Tt + j];
            s    = (arow[j] > 0.f) ? s : NEG_INF;
            v[t] = s;
            m    = fmaxf(m, s);
        }
#pragma unroll
        for (int o = 16; o; o >>= 1) m = fmaxf(m, __shfl_xor_sync(0xffffffff, m, o));
        float sum = 0.f;
#pragma unroll
        for (int t = 0; t < 16; t++) {
            v[t] = __expf(v[t] - m);
            sum += v[t];
        }
#pragma unroll
        for (int o = 16; o; o >>= 1) sum += __shfl_xor_sync(0xffffffff, sum, o);
        float inv = 1.f / sum;
#pragma unroll
        for (int t = 0; t < 16; t++) sc[r * Tt + lane + 32 * t] = v[t] * inv;
    }

    // ================= AV phase: 4 rowgroups x 4 j-quarters =================
    const int rg = warp & 3;   // rows 4rg..4rg+3
    const int jq = warp >> 2;  // j-quarter within each chunk (64 js)

    u64 a0x = 0, a0y = 0, a1x = 0, a1y = 0;
    u64 a2x = 0, a2y = 0, a3x = 0, a3y = 0;

    for (int jc = 0; jc < Tt; jc += JT) {
        __syncthreads();
#pragma unroll 4
        for (int t = 0; t < 16; t++) {
            int f4 = tid + 512 * t;
            int r = f4 >> 5, c = f4 & 31;
            ((float4*)(qs + r * 132))[c] =
                ((const float4*)(x + (size_t)(b * Tt + jc + r) * Cc))[c];
        }
        __syncthreads();

        const float* w0row = sc + (4 * rg + 0) * Tt + jc;
        const float* w1row = sc + (4 * rg + 1) * Tt + jc;
        const float* w2row = sc + (4 * rg + 2) * Tt + jc;
        const float* w3row = sc + (4 * rg + 3) * Tt + jc;
        const int jbase = jq * 64;
#pragma unroll 4
        for (int jj = jbase; jj < jbase + 64; jj++) {
            u64 w0 = dup2(w0row[jj]);
            u64 w1 = dup2(w1row[jj]);
            u64 w2 = dup2(w2row[jj]);
            u64 w3 = dup2(w3row[jj]);
            ulonglong2 xv = ((const ulonglong2*)(qs + jj * 132))[lane];
            fma2(a0x, w0, xv.x); fma2(a0y, w0, xv.y);
            fma2(a1x, w1, xv.x); fma2(a1y, w1, xv.y);
            fma2(a2x, w2, xv.x); fma2(a2y, w2, xv.y);
            fma2(a3x, w3, xv.x); fma2(a3y, w3, xv.y);
        }
    }
    __syncthreads();

    // reduce j-quarters through smem (reuse qs): buf[jq][row16][lane]
    ulonglong2* buf = (ulonglong2*)qs;
    if (jq != 0) {
        int base = ((jq * 16) + 4 * rg) * 32 + lane;
        buf[base + 0 * 32] = make_ulonglong2(a0x, a0y);
        buf[base + 1 * 32] = make_ulonglong2(a1x, a1y);
        buf[base + 2 * 32] = make_ulonglong2(a2x, a2y);
        buf[base + 3 * 32] = make_ulonglong2(a3x, a3y);
    }
    __syncthreads();
    if (jq == 0) {
#pragma unroll
        for (int q = 1; q < 4; q++) {
            int base = ((q * 16) + 4 * rg) * 32 + lane;
            ulonglong2 b0 = buf[base + 0 * 32];
            ulonglong2 b1 = buf[base + 1 * 32];
            ulonglong2 b2 = buf[base + 2 * 32];
            ulonglong2 b3 = buf[base + 3 * 32];
            a0x = add2(a0x, b0.x); a0y = add2(a0y, b0.y);
            a1x = add2(a1x, b1.x); a1y = add2(a1y, b1.y);
            a2x = add2(a2x, b2.x); a2y = add2(a2y, b2.y);
            a3x = add2(a3x, b3.x); a3y = add2(a3y, b3.y);
        }
        float4 o0 = make_float4(lo2(a0x), hi2(a0x), lo2(a0y), hi2(a0y));
        float4 o1 = make_float4(lo2(a1x), hi2(a1x), lo2(a1y), hi2(a1y));
        float4 o2 = make_float4(lo2(a2x), hi2(a2x), lo2(a2y), hi2(a2y));
        float4 o3 = make_float4(lo2(a3x), hi2(a3x), lo2(a3y), hi2(a3y));
        ((float4*)(out + (size_t)(b * Tt + i0 + 4 * rg + 0) * Cc))[lane] = o0;
        ((float4*)(out + (size_t)(b * Tt + i0 + 4 * rg + 1) * Cc))[lane] = o1;
        ((float4*)(out + (size_t)(b * Tt + i0 + 4 * rg + 2) * Cc))[lane] = o2;
        ((float4*)(out + (size_t)(b * Tt + i0 + 4 * rg + 3) * Cc))[lane] = o3;
    }
}

// ---------------------------------------------------------------------------
extern "C" void kernel_launch(void* const* d_in, const int* in_sizes, int n_in,
                              void* d_out, int out_size) {
    const float* x   = (const float*)d_in[0];
    const float* adj = (const float*)d_in[1];
    const float* WQ  = (const float*)d_in[2];
    const float* WK  = (const float*)d_in[3];
    const float* p   = (const float*)d_in[4];
    float*       out = (float*)d_out;

    qk_kernel<<<dim3((Bb * Tt) / 16, 2), 256>>>(x, WQ, WK);

    cudaFuncSetAttribute(attn_kernel, cudaFuncAttributeMaxDynamicSharedMemorySize,
                         SMEM_BYTES);
    attn_kernel<<<dim3(Tt / TI, Bb), 512, SMEM_BYTES>>>(x, adj, p, out);
}